// round 7
// baseline (speedup 1.0000x reference)
#include <cuda_runtime.h>
#include <cuda_fp16.h>

// Problem constants (match reference)
#define T_STEPS 100
#define BATCH   32
#define NIN     1024
#define NOUT    512
#define K_TOT   (T_STEPS * BATCH)   // 3200

#define LR_LTP  1e-4f
#define DECAY   0.951229424500714f   // exp(-1/20)
#define D25     0.2865047968601901f  // DECAY^25
#define D50     0.0820849986238988f  // DECAY^50

// T chunking: 4 chunks of 25 steps
#define NCHUNK 4
#define TC     25

// Spike lists: segment per (column, b, chunk); ordered by t within a segment.
#define SEGS  (BATCH * NCHUNK)      // 128 segments per column
#define CAPS2 16                    // Binom(25,0.05): mean 1.25 -> P(>16) ~ 0

// Device scratch (allocation-free). Referenced ONLY from device code.
__device__ __half g_pre_tr_h [K_TOT * NIN];          // [k, i] fp16 history
__device__ __half g_post_tr_h[K_TOT * NOUT];         // [k, o]
__device__ float  g_pre_end [NCHUNK * BATCH * NIN];  // fp32 local chunk-ends
__device__ float  g_post_end[NCHUNK * BATCH * NOUT];
__device__ float  g_Sp [NOUT * NIN];                 // LTP sums, [o, i]
__device__ float  g_SdT[NIN * NOUT];                 // LTD sums TRANSPOSED [i, o]
__device__ int    g_post_list[NOUT * SEGS * CAPS2];
__device__ int    g_pre_list [NIN  * SEGS * CAPS2];
__device__ int    g_post_cnt [NOUT * SEGS];
__device__ int    g_pre_cnt  [NIN  * SEGS];

// ---------------------------------------------------------------------------
// Kernel A: chunked local trace recurrence + list build, both populations.
// Thread = (chunk c, b, col). Chunk 0 starts from trace0 (true values);
// chunks 1..3 start from 0 (fixed up in kernel B). Writes fp16 history,
// fp32 local chunk-end, and its own (col,b,c) spike-time segment.
// ---------------------------------------------------------------------------
#define A_PRE_CTAS  ((NCHUNK * BATCH * NIN ) / 256)  // 512
#define A_POST_CTAS ((NCHUNK * BATCH * NOUT) / 256)  // 256

__global__ void __launch_bounds__(256)
trace_partial_kernel(const float* __restrict__ pre_spikes,
                     const float* __restrict__ post_spikes,
                     const float* __restrict__ pre_trace0,
                     const float* __restrict__ post_trace0)
{
    if (blockIdx.x < A_PRE_CTAS) {
        const int g   = blockIdx.x * 256 + threadIdx.x;   // (c*BATCH+b)*NIN + i
        const int c   = g >> 15;
        const int idx = g & 32767;                        // b*NIN + i
        const int b   = idx >> 10;
        const int i   = idx & 1023;
        int* seg = &g_pre_list[((i * BATCH + b) * NCHUNK + c) * CAPS2];
        int  cnt = 0;
        float tr = (c == 0) ? pre_trace0[idx] : 0.f;
        const int t0 = c * TC;
        #pragma unroll 5
        for (int p = 0; p < TC; ++p) {
            int t = t0 + p;
            float s = pre_spikes[t * (BATCH * NIN) + idx];
            tr = tr * DECAY + s;
            g_pre_tr_h[t * (BATCH * NIN) + idx] = __float2half_rn(tr);
            if (s > 0.5f && cnt < CAPS2) seg[cnt++] = t * BATCH + b;
        }
        g_pre_cnt[(i * BATCH + b) * NCHUNK + c] = cnt;
        g_pre_end[g] = tr;
    } else {
        const int g   = (blockIdx.x - A_PRE_CTAS) * 256 + threadIdx.x;
        const int c   = g >> 14;
        const int idx = g & 16383;                        // b*NOUT + o
        const int b   = idx >> 9;
        const int o   = idx & 511;
        int* seg = &g_post_list[((o * BATCH + b) * NCHUNK + c) * CAPS2];
        int  cnt = 0;
        float tr = (c == 0) ? post_trace0[idx] : 0.f;
        const int t0 = c * TC;
        #pragma unroll 5
        for (int p = 0; p < TC; ++p) {
            int t = t0 + p;
            float s = post_spikes[t * (BATCH * NOUT) + idx];
            tr = tr * DECAY + s;
            g_post_tr_h[t * (BATCH * NOUT) + idx] = __float2half_rn(tr);
            if (s > 0.5f && cnt < CAPS2) seg[cnt++] = t * BATCH + b;
        }
        g_post_cnt[(o * BATCH + b) * NCHUNK + c] = cnt;
        g_post_end[g] = tr;
    }
}

// ---------------------------------------------------------------------------
// Kernel B: fixup. Thread = (chunk c in 1..3, b, col). carry = true end of
// chunk c-1, closed-form fp32 from local ends. Adds decay^(p+1)*carry to its
// 25 fp16 history entries. Chunk-3 threads emit final traces in pure fp32.
// ---------------------------------------------------------------------------
#define B_PRE_CTAS  ((3 * BATCH * NIN ) / 256)  // 384
#define B_POST_CTAS ((3 * BATCH * NOUT) / 256)  // 192

__global__ void __launch_bounds__(256)
trace_fixup_kernel(float* __restrict__ out_pre_tr,
                   float* __restrict__ out_post_tr)
{
    if (blockIdx.x < B_PRE_CTAS) {
        const int g   = blockIdx.x * 256 + threadIdx.x;
        const int c   = (g >> 15) + 1;                    // 1..3
        const int idx = g & 32767;
        float e0 = g_pre_end[idx];                        // true end of chunk 0
        float carry;
        if (c == 1) carry = e0;
        else {
            float e1 = g_pre_end[32768 + idx];
            if (c == 2) carry = fmaf(D25, e0, e1);
            else {
                float e2 = g_pre_end[65536 + idx];
                carry = e2 + D25 * e1 + D50 * e0;         // true end of chunk 2
            }
        }
        float f = DECAY;
        const int t0 = c * TC;
        #pragma unroll 5
        for (int p = 0; p < TC; ++p) {
            int a = (t0 + p) * (BATCH * NIN) + idx;
            float v = __half2float(g_pre_tr_h[a]) + f * carry;
            g_pre_tr_h[a] = __float2half_rn(v);
            f *= DECAY;
        }
        if (c == 3) {
            float e3 = g_pre_end[98304 + idx];
            out_pre_tr[idx] = fmaf(D25, carry, e3);       // exact fp32 final trace
        }
    } else {
        const int g   = (blockIdx.x - B_PRE_CTAS) * 256 + threadIdx.x;
        const int c   = (g >> 14) + 1;
        const int idx = g & 16383;
        float e0 = g_post_end[idx];
        float carry;
        if (c == 1) carry = e0;
        else {
            float e1 = g_post_end[16384 + idx];
            if (c == 2) carry = fmaf(D25, e0, e1);
            else {
                float e2 = g_post_end[32768 + idx];
                carry = e2 + D25 * e1 + D50 * e0;
            }
        }
        float f = DECAY;
        const int t0 = c * TC;
        #pragma unroll 5
        for (int p = 0; p < TC; ++p) {
            int a = (t0 + p) * (BATCH * NOUT) + idx;
            float v = __half2float(g_post_tr_h[a]) + f * carry;
            g_post_tr_h[a] = __float2half_rn(v);
            f *= DECAY;
        }
        if (c == 3) {
            float e3 = g_post_end[49152 + idx];
            out_post_tr[idx] = fmaf(D25, carry, e3);
        }
    }
}

// ---------------------------------------------------------------------------
// Fused gathers, one launch, 1536 CTAs x 256 threads:
//   bid <  NIN : LTD for input i   -> writes SdT[i, :] (coalesced)
//   bid >= NIN : LTP for output o  -> writes Sp[o, :]  (coalesced)
// Stage compact list: 4 warp-scans over 128 segment counts + cross-warp base,
// then 2-threads-per-segment copy; unroll-8 accumulation (8 loads in flight).
// ---------------------------------------------------------------------------
__global__ void __launch_bounds__(256)
gathers_fused_kernel()
{
    __shared__ int slist[SEGS * CAPS2];   // 2048
    __shared__ int s_cnt[SEGS];
    __shared__ int s_off[SEGS];
    __shared__ int s_wsum[4];
    __shared__ int s_total;

    const int bid = blockIdx.x;
    const int tid = threadIdx.x;
    const bool is_ltd = (bid < NIN);
    const int  col    = is_ltd ? bid : (bid - NIN);

    if (tid < SEGS) {
        int c = is_ltd ? g_pre_cnt [col * SEGS + tid]
                       : g_post_cnt[col * SEGS + tid];
        int lane = tid & 31, w = tid >> 5;
        int x = c;
        #pragma unroll
        for (int off = 1; off < 32; off <<= 1) {
            int y = __shfl_up_sync(0xffffffffu, x, off);
            if (lane >= off) x += y;
        }
        s_cnt[tid] = c;
        s_off[tid] = x - c;                 // exclusive within warp
        if (lane == 31) s_wsum[w] = x;
    }
    __syncthreads();
    if (tid == 0) {
        int b0 = 0, b1 = s_wsum[0], b2 = b1 + s_wsum[1], b3 = b2 + s_wsum[2];
        s_total = b3 + s_wsum[3];
        s_wsum[0] = b0; s_wsum[1] = b1; s_wsum[2] = b2; s_wsum[3] = b3;
    }
    __syncthreads();
    {
        int s = tid >> 1;                   // 2 threads per segment
        int c = s_cnt[s], base = s_off[s] + s_wsum[s >> 5];
        const int* seg = is_ltd ? &g_pre_list [(col * SEGS + s) * CAPS2]
                                : &g_post_list[(col * SEGS + s) * CAPS2];
        for (int j = tid & 1; j < c; j += 2) slist[base + j] = seg[j];
    }
    __syncthreads();

    const int L = s_total;

    if (is_ltd) {
        // LTD: 256 threads x half2 (2 outputs) = NOUT; coalesced SdT write.
        const int i = col;
        float a0 = 0.f, a1 = 0.f, b0 = 0.f, b1 = 0.f;
        int j = 0;
        for (; j + 8 <= L; j += 8) {
            unsigned v0 = *reinterpret_cast<const unsigned*>(&g_post_tr_h[slist[j+0] * NOUT + tid * 2]);
            unsigned v1 = *reinterpret_cast<const unsigned*>(&g_post_tr_h[slist[j+1] * NOUT + tid * 2]);
            unsigned v2 = *reinterpret_cast<const unsigned*>(&g_post_tr_h[slist[j+2] * NOUT + tid * 2]);
            unsigned v3 = *reinterpret_cast<const unsigned*>(&g_post_tr_h[slist[j+3] * NOUT + tid * 2]);
            unsigned v4 = *reinterpret_cast<const unsigned*>(&g_post_tr_h[slist[j+4] * NOUT + tid * 2]);
            unsigned v5 = *reinterpret_cast<const unsigned*>(&g_post_tr_h[slist[j+5] * NOUT + tid * 2]);
            unsigned v6 = *reinterpret_cast<const unsigned*>(&g_post_tr_h[slist[j+6] * NOUT + tid * 2]);
            unsigned v7 = *reinterpret_cast<const unsigned*>(&g_post_tr_h[slist[j+7] * NOUT + tid * 2]);
            float2 f;
            f = __half22float2(*reinterpret_cast<__half2*>(&v0)); a0 += f.x; a1 += f.y;
            f = __half22float2(*reinterpret_cast<__half2*>(&v1)); b0 += f.x; b1 += f.y;
            f = __half22float2(*reinterpret_cast<__half2*>(&v2)); a0 += f.x; a1 += f.y;
            f = __half22float2(*reinterpret_cast<__half2*>(&v3)); b0 += f.x; b1 += f.y;
            f = __half22float2(*reinterpret_cast<__half2*>(&v4)); a0 += f.x; a1 += f.y;
            f = __half22float2(*reinterpret_cast<__half2*>(&v5)); b0 += f.x; b1 += f.y;
            f = __half22float2(*reinterpret_cast<__half2*>(&v6)); a0 += f.x; a1 += f.y;
            f = __half22float2(*reinterpret_cast<__half2*>(&v7)); b0 += f.x; b1 += f.y;
        }
        for (; j < L; ++j) {
            unsigned v = *reinterpret_cast<const unsigned*>(&g_post_tr_h[slist[j] * NOUT + tid * 2]);
            float2 f = __half22float2(*reinterpret_cast<__half2*>(&v));
            a0 += f.x; a1 += f.y;
        }
        *reinterpret_cast<float2*>(&g_SdT[i * NOUT + tid * 2]) =
            make_float2(a0 + b0, a1 + b1);
    } else {
        // LTP: 256 threads x uint2 (4 inputs) = NIN; coalesced Sp write.
        const int o = col;
        float a0 = 0.f, a1 = 0.f, a2 = 0.f, a3 = 0.f;
        float b0 = 0.f, b1 = 0.f, b2 = 0.f, b3 = 0.f;
        int j = 0;
        for (; j + 8 <= L; j += 8) {
            uint2 v0 = *reinterpret_cast<const uint2*>(&g_pre_tr_h[slist[j+0] * NIN + tid * 4]);
            uint2 v1 = *reinterpret_cast<const uint2*>(&g_pre_tr_h[slist[j+1] * NIN + tid * 4]);
            uint2 v2 = *reinterpret_cast<const uint2*>(&g_pre_tr_h[slist[j+2] * NIN + tid * 4]);
            uint2 v3 = *reinterpret_cast<const uint2*>(&g_pre_tr_h[slist[j+3] * NIN + tid * 4]);
            uint2 v4 = *reinterpret_cast<const uint2*>(&g_pre_tr_h[slist[j+4] * NIN + tid * 4]);
            uint2 v5 = *reinterpret_cast<const uint2*>(&g_pre_tr_h[slist[j+5] * NIN + tid * 4]);
            uint2 v6 = *reinterpret_cast<const uint2*>(&g_pre_tr_h[slist[j+6] * NIN + tid * 4]);
            uint2 v7 = *reinterpret_cast<const uint2*>(&g_pre_tr_h[slist[j+7] * NIN + tid * 4]);
            float2 f;
            f = __half22float2(*reinterpret_cast<__half2*>(&v0.x)); a0 += f.x; a1 += f.y;
            f = __half22float2(*reinterpret_cast<__half2*>(&v0.y)); a2 += f.x; a3 += f.y;
            f = __half22float2(*reinterpret_cast<__half2*>(&v1.x)); b0 += f.x; b1 += f.y;
            f = __half22float2(*reinterpret_cast<__half2*>(&v1.y)); b2 += f.x; b3 += f.y;
            f = __half22float2(*reinterpret_cast<__half2*>(&v2.x)); a0 += f.x; a1 += f.y;
            f = __half22float2(*reinterpret_cast<__half2*>(&v2.y)); a2 += f.x; a3 += f.y;
            f = __half22float2(*reinterpret_cast<__half2*>(&v3.x)); b0 += f.x; b1 += f.y;
            f = __half22float2(*reinterpret_cast<__half2*>(&v3.y)); b2 += f.x; b3 += f.y;
            f = __half22float2(*reinterpret_cast<__half2*>(&v4.x)); a0 += f.x; a1 += f.y;
            f = __half22float2(*reinterpret_cast<__half2*>(&v4.y)); a2 += f.x; a3 += f.y;
            f = __half22float2(*reinterpret_cast<__half2*>(&v5.x)); b0 += f.x; b1 += f.y;
            f = __half22float2(*reinterpret_cast<__half2*>(&v5.y)); b2 += f.x; b3 += f.y;
            f = __half22float2(*reinterpret_cast<__half2*>(&v6.x)); a0 += f.x; a1 += f.y;
            f = __half22float2(*reinterpret_cast<__half2*>(&v6.y)); a2 += f.x; a3 += f.y;
            f = __half22float2(*reinterpret_cast<__half2*>(&v7.x)); b0 += f.x; b1 += f.y;
            f = __half22float2(*reinterpret_cast<__half2*>(&v7.y)); b2 += f.x; b3 += f.y;
        }
        for (; j < L; ++j) {
            uint2 v = *reinterpret_cast<const uint2*>(&g_pre_tr_h[slist[j] * NIN + tid * 4]);
            float2 f;
            f = __half22float2(*reinterpret_cast<__half2*>(&v.x)); a0 += f.x; a1 += f.y;
            f = __half22float2(*reinterpret_cast<__half2*>(&v.y)); a2 += f.x; a3 += f.y;
        }
        *reinterpret_cast<float4*>(&g_Sp[o * NIN + tid * 4]) =
            make_float4(a0 + b0, a1 + b1, a2 + b2, a3 + b3);
    }
}

// ---------------------------------------------------------------------------
// Combine with smem tile-transpose of SdT: all global accesses coalesced.
// Grid (NIN/32, NOUT/32), 256 threads; 32x32 tile, 4 elems/thread.
// delta_w[o,i] = s * ((1-w)*Sp[o,i] - w*SdT[i,o])
// ---------------------------------------------------------------------------
__global__ void __launch_bounds__(256)
combine_kernel(const float* __restrict__ weight,
               float* __restrict__ delta_w)
{
    __shared__ float s_t[32][33];

    const int i0 = blockIdx.x * 32;
    const int o0 = blockIdx.y * 32;
    const int tid = threadIdx.x;

    // Load SdT tile (rows = i), coalesced float4
    {
        int r  = tid >> 3;            // 0..31 (i-local)
        int c4 = (tid & 7) * 4;       // o-local
        float4 v = *reinterpret_cast<const float4*>(&g_SdT[(i0 + r) * NOUT + o0 + c4]);
        s_t[r][c4 + 0] = v.x; s_t[r][c4 + 1] = v.y;
        s_t[r][c4 + 2] = v.z; s_t[r][c4 + 3] = v.w;
    }
    __syncthreads();

    const float s = LR_LTP / (float)BATCH;
    const int ol = tid >> 3;          // o-local 0..31
    const int il = (tid & 7) * 4;     // i-local
    const int base = (o0 + ol) * NIN + i0 + il;
    float4 w = *reinterpret_cast<const float4*>(&weight[base]);
    float4 p = *reinterpret_cast<const float4*>(&g_Sp[base]);
    float4 r;
    r.x = s * ((1.f - w.x) * p.x - w.x * s_t[il + 0][ol]);
    r.y = s * ((1.f - w.y) * p.y - w.y * s_t[il + 1][ol]);
    r.z = s * ((1.f - w.z) * p.z - w.z * s_t[il + 2][ol]);
    r.w = s * ((1.f - w.w) * p.w - w.w * s_t[il + 3][ol]);
    *reinterpret_cast<float4*>(&delta_w[base]) = r;
}

// ---------------------------------------------------------------------------
extern "C" void kernel_launch(void* const* d_in, const int* in_sizes, int n_in,
                              void* d_out, int out_size)
{
    const float* weight      = (const float*)d_in[0];  // [NOUT, NIN]
    const float* pre_spikes  = (const float*)d_in[1];  // [T, B, NIN]
    const float* post_spikes = (const float*)d_in[2];  // [T, B, NOUT]
    const float* pre_trace0  = (const float*)d_in[3];  // [B, NIN]
    const float* post_trace0 = (const float*)d_in[4];  // [B, NOUT]

    float* out         = (float*)d_out;
    float* out_delta_w = out;                              // 512*1024
    float* out_pre_tr  = out + NOUT * NIN;                 // 32*1024
    float* out_post_tr = out + NOUT * NIN + BATCH * NIN;   // 32*512

    // 1) Chunked local traces + list builds (196K threads)
    trace_partial_kernel<<<A_PRE_CTAS + A_POST_CTAS, 256>>>(
        pre_spikes, post_spikes, pre_trace0, post_trace0);

    // 2) Carry fixup (147K threads) + exact fp32 final-trace outputs
    trace_fixup_kernel<<<B_PRE_CTAS + B_POST_CTAS, 256>>>(out_pre_tr, out_post_tr);

    // 3) Both sparse gathers in one launch (coalesced stores both sides)
    gathers_fused_kernel<<<NIN + NOUT, 256>>>();

    // 4) Combine with tiled transpose of SdT
    dim3 cgrid(NIN / 32, NOUT / 32);
    combine_kernel<<<cgrid, 256>>>(weight, out_delta_w);
}

// round 8
// speedup vs baseline: 1.1533x; 1.1533x over previous
#include <cuda_runtime.h>
#include <cuda_fp16.h>

// Problem constants (match reference)
#define T_STEPS 100
#define BATCH   32
#define NIN     1024
#define NOUT    512
#define K_TOT   (T_STEPS * BATCH)   // 3200

#define LR_LTP  1e-4f
#define DECAY   0.951229424500714f  // exp(-1/20)

// Spike lists: one segment per (column, batch-lane b); ordered by t within a
// segment, segments concatenated in b order => deterministic sum order.
#define NSEG  BATCH                 // 32 segments per column
#define CAPS  32                    // per-segment capacity (Binom(100,0.05): mean 5)

// Device scratch (allocation-free). Referenced ONLY from device code.
__device__ __half g_pre_tr_h [K_TOT * NIN];   // [k, i] fp16 trace history
__device__ __half g_post_tr_h[K_TOT * NOUT];  // [k, o]
__device__ float  g_Sp [NOUT * NIN];          // LTP sums [o, i]
__device__ float  g_SdT[NIN * NOUT];          // LTD sums TRANSPOSED [i, o]
__device__ int    g_post_list[NOUT * NSEG * CAPS];
__device__ int    g_pre_list [NIN  * NSEG * CAPS];
__device__ int    g_post_cnt [NOUT * NSEG];
__device__ int    g_pre_cnt  [NIN  * NSEG];

// ---------------------------------------------------------------------------
// Fused trace recurrence + spike-list build, both populations, one launch.
// Thread = (b, col); walks t with 10-deep batched loads (MLP=10), writes fp16
// history row k = t*BATCH+b, appends spike times to its own (col,b) segment
// (single ordered writer -> deterministic), emits exact fp32 final trace.
// ---------------------------------------------------------------------------
#define PRE_CTAS  ((BATCH * NIN ) / 256)   // 128
#define POST_CTAS ((BATCH * NOUT) / 256)   // 64
#define UB 10                              // load batch depth (100 = 10*10)

__global__ void __launch_bounds__(256)
traces_fused_kernel(const float* __restrict__ pre_spikes,
                    const float* __restrict__ post_spikes,
                    const float* __restrict__ pre_trace0,
                    const float* __restrict__ post_trace0,
                    float* __restrict__ out_pre_tr,
                    float* __restrict__ out_post_tr)
{
    if (blockIdx.x < PRE_CTAS) {
        const int idx = blockIdx.x * 256 + threadIdx.x;   // b*NIN + i
        const int b = idx >> 10;
        const int i = idx & 1023;
        int* seg = &g_pre_list[(i * NSEG + b) * CAPS];
        int  c   = 0;
        float tr = pre_trace0[idx];
        for (int t0 = 0; t0 < T_STEPS; t0 += UB) {
            float s[UB];
            #pragma unroll
            for (int u = 0; u < UB; ++u)
                s[u] = __ldcs(&pre_spikes[(t0 + u) * (BATCH * NIN) + idx]);
            #pragma unroll
            for (int u = 0; u < UB; ++u) {
                tr = tr * DECAY + s[u];
                g_pre_tr_h[(t0 + u) * (BATCH * NIN) + idx] = __float2half_rn(tr);
                if (s[u] > 0.5f && c < CAPS) seg[c++] = (t0 + u) * BATCH + b;
            }
        }
        g_pre_cnt[i * NSEG + b] = c;
        out_pre_tr[idx] = tr;
    } else {
        const int idx = (blockIdx.x - PRE_CTAS) * 256 + threadIdx.x;  // b*NOUT + o
        const int b = idx >> 9;
        const int o = idx & 511;
        int* seg = &g_post_list[(o * NSEG + b) * CAPS];
        int  c   = 0;
        float tr = post_trace0[idx];
        for (int t0 = 0; t0 < T_STEPS; t0 += UB) {
            float s[UB];
            #pragma unroll
            for (int u = 0; u < UB; ++u)
                s[u] = __ldcs(&post_spikes[(t0 + u) * (BATCH * NOUT) + idx]);
            #pragma unroll
            for (int u = 0; u < UB; ++u) {
                tr = tr * DECAY + s[u];
                g_post_tr_h[(t0 + u) * (BATCH * NOUT) + idx] = __float2half_rn(tr);
                if (s[u] > 0.5f && c < CAPS) seg[c++] = (t0 + u) * BATCH + b;
            }
        }
        g_post_cnt[o * NSEG + b] = c;
        out_post_tr[idx] = tr;
    }
}

// ---------------------------------------------------------------------------
// Fused gathers, one launch, 1536 CTAs x 256 threads:
//   bid <  NIN : LTD for input i   -> writes SdT[i, :] (coalesced float2)
//   bid >= NIN : LTP for output o  -> writes Sp[o, :]  (coalesced float4)
// Stage compact list via warp-scan + 8-threads-per-segment copy, then
// unroll-8 accumulation (8 independent L2 loads in flight).
// ---------------------------------------------------------------------------
__global__ void __launch_bounds__(256)
gathers_fused_kernel()
{
    __shared__ int slist[NSEG * CAPS];
    __shared__ int s_cnt[NSEG];
    __shared__ int s_off[NSEG];
    __shared__ int s_total;

    const int bid = blockIdx.x;
    const int tid = threadIdx.x;
    const bool is_ltd = (bid < NIN);
    const int  col    = is_ltd ? bid : (bid - NIN);

    if (tid < 32) {
        int c = is_ltd ? g_pre_cnt[col * NSEG + tid]
                       : g_post_cnt[col * NSEG + tid];
        int x = c;
        #pragma unroll
        for (int off = 1; off < 32; off <<= 1) {
            int y = __shfl_up_sync(0xffffffffu, x, off);
            if (tid >= off) x += y;
        }
        s_cnt[tid] = c;
        s_off[tid] = x - c;
        if (tid == 31) s_total = x;
    }
    __syncthreads();
    {
        int s = tid >> 3;                 // 8 threads per segment
        int c = s_cnt[s], base = s_off[s];
        const int* seg = is_ltd ? &g_pre_list [(col * NSEG + s) * CAPS]
                                : &g_post_list[(col * NSEG + s) * CAPS];
        for (int j = tid & 7; j < c; j += 8) slist[base + j] = seg[j];
    }
    __syncthreads();

    const int L = s_total;

    if (is_ltd) {
        // LTD: 256 threads x half2 (2 outputs) = NOUT; coalesced SdT write.
        const int i = col;
        float a0 = 0.f, a1 = 0.f, b0 = 0.f, b1 = 0.f;
        int j = 0;
        for (; j + 8 <= L; j += 8) {
            unsigned v0 = *reinterpret_cast<const unsigned*>(&g_post_tr_h[slist[j+0] * NOUT + tid * 2]);
            unsigned v1 = *reinterpret_cast<const unsigned*>(&g_post_tr_h[slist[j+1] * NOUT + tid * 2]);
            unsigned v2 = *reinterpret_cast<const unsigned*>(&g_post_tr_h[slist[j+2] * NOUT + tid * 2]);
            unsigned v3 = *reinterpret_cast<const unsigned*>(&g_post_tr_h[slist[j+3] * NOUT + tid * 2]);
            unsigned v4 = *reinterpret_cast<const unsigned*>(&g_post_tr_h[slist[j+4] * NOUT + tid * 2]);
            unsigned v5 = *reinterpret_cast<const unsigned*>(&g_post_tr_h[slist[j+5] * NOUT + tid * 2]);
            unsigned v6 = *reinterpret_cast<const unsigned*>(&g_post_tr_h[slist[j+6] * NOUT + tid * 2]);
            unsigned v7 = *reinterpret_cast<const unsigned*>(&g_post_tr_h[slist[j+7] * NOUT + tid * 2]);
            float2 f;
            f = __half22float2(*reinterpret_cast<__half2*>(&v0)); a0 += f.x; a1 += f.y;
            f = __half22float2(*reinterpret_cast<__half2*>(&v1)); b0 += f.x; b1 += f.y;
            f = __half22float2(*reinterpret_cast<__half2*>(&v2)); a0 += f.x; a1 += f.y;
            f = __half22float2(*reinterpret_cast<__half2*>(&v3)); b0 += f.x; b1 += f.y;
            f = __half22float2(*reinterpret_cast<__half2*>(&v4)); a0 += f.x; a1 += f.y;
            f = __half22float2(*reinterpret_cast<__half2*>(&v5)); b0 += f.x; b1 += f.y;
            f = __half22float2(*reinterpret_cast<__half2*>(&v6)); a0 += f.x; a1 += f.y;
            f = __half22float2(*reinterpret_cast<__half2*>(&v7)); b0 += f.x; b1 += f.y;
        }
        for (; j < L; ++j) {
            unsigned v = *reinterpret_cast<const unsigned*>(&g_post_tr_h[slist[j] * NOUT + tid * 2]);
            float2 f = __half22float2(*reinterpret_cast<__half2*>(&v));
            a0 += f.x; a1 += f.y;
        }
        *reinterpret_cast<float2*>(&g_SdT[i * NOUT + tid * 2]) =
            make_float2(a0 + b0, a1 + b1);
    } else {
        // LTP: 256 threads x uint2 (4 inputs) = NIN; coalesced Sp write.
        const int o = col;
        float a0 = 0.f, a1 = 0.f, a2 = 0.f, a3 = 0.f;
        float b0 = 0.f, b1 = 0.f, b2 = 0.f, b3 = 0.f;
        int j = 0;
        for (; j + 8 <= L; j += 8) {
            uint2 v0 = *reinterpret_cast<const uint2*>(&g_pre_tr_h[slist[j+0] * NIN + tid * 4]);
            uint2 v1 = *reinterpret_cast<const uint2*>(&g_pre_tr_h[slist[j+1] * NIN + tid * 4]);
            uint2 v2 = *reinterpret_cast<const uint2*>(&g_pre_tr_h[slist[j+2] * NIN + tid * 4]);
            uint2 v3 = *reinterpret_cast<const uint2*>(&g_pre_tr_h[slist[j+3] * NIN + tid * 4]);
            uint2 v4 = *reinterpret_cast<const uint2*>(&g_pre_tr_h[slist[j+4] * NIN + tid * 4]);
            uint2 v5 = *reinterpret_cast<const uint2*>(&g_pre_tr_h[slist[j+5] * NIN + tid * 4]);
            uint2 v6 = *reinterpret_cast<const uint2*>(&g_pre_tr_h[slist[j+6] * NIN + tid * 4]);
            uint2 v7 = *reinterpret_cast<const uint2*>(&g_pre_tr_h[slist[j+7] * NIN + tid * 4]);
            float2 f;
            f = __half22float2(*reinterpret_cast<__half2*>(&v0.x)); a0 += f.x; a1 += f.y;
            f = __half22float2(*reinterpret_cast<__half2*>(&v0.y)); a2 += f.x; a3 += f.y;
            f = __half22float2(*reinterpret_cast<__half2*>(&v1.x)); b0 += f.x; b1 += f.y;
            f = __half22float2(*reinterpret_cast<__half2*>(&v1.y)); b2 += f.x; b3 += f.y;
            f = __half22float2(*reinterpret_cast<__half2*>(&v2.x)); a0 += f.x; a1 += f.y;
            f = __half22float2(*reinterpret_cast<__half2*>(&v2.y)); a2 += f.x; a3 += f.y;
            f = __half22float2(*reinterpret_cast<__half2*>(&v3.x)); b0 += f.x; b1 += f.y;
            f = __half22float2(*reinterpret_cast<__half2*>(&v3.y)); b2 += f.x; b3 += f.y;
            f = __half22float2(*reinterpret_cast<__half2*>(&v4.x)); a0 += f.x; a1 += f.y;
            f = __half22float2(*reinterpret_cast<__half2*>(&v4.y)); a2 += f.x; a3 += f.y;
            f = __half22float2(*reinterpret_cast<__half2*>(&v5.x)); b0 += f.x; b1 += f.y;
            f = __half22float2(*reinterpret_cast<__half2*>(&v5.y)); b2 += f.x; b3 += f.y;
            f = __half22float2(*reinterpret_cast<__half2*>(&v6.x)); a0 += f.x; a1 += f.y;
            f = __half22float2(*reinterpret_cast<__half2*>(&v6.y)); a2 += f.x; a3 += f.y;
            f = __half22float2(*reinterpret_cast<__half2*>(&v7.x)); b0 += f.x; b1 += f.y;
            f = __half22float2(*reinterpret_cast<__half2*>(&v7.y)); b2 += f.x; b3 += f.y;
        }
        for (; j < L; ++j) {
            uint2 v = *reinterpret_cast<const uint2*>(&g_pre_tr_h[slist[j] * NIN + tid * 4]);
            float2 f;
            f = __half22float2(*reinterpret_cast<__half2*>(&v.x)); a0 += f.x; a1 += f.y;
            f = __half22float2(*reinterpret_cast<__half2*>(&v.y)); a2 += f.x; a3 += f.y;
        }
        *reinterpret_cast<float4*>(&g_Sp[o * NIN + tid * 4]) =
            make_float4(a0 + b0, a1 + b1, a2 + b2, a3 + b3);
    }
}

// ---------------------------------------------------------------------------
// Combine with smem tile-transpose of SdT: all global accesses coalesced.
// Grid (NIN/32, NOUT/32), 256 threads; 32x32 tile, 4 elems/thread.
// delta_w[o,i] = s * ((1-w)*Sp[o,i] - w*SdT[i,o])
// ---------------------------------------------------------------------------
__global__ void __launch_bounds__(256)
combine_kernel(const float* __restrict__ weight,
               float* __restrict__ delta_w)
{
    __shared__ float s_t[32][33];

    const int i0 = blockIdx.x * 32;
    const int o0 = blockIdx.y * 32;
    const int tid = threadIdx.x;

    {
        int r  = tid >> 3;            // 0..31 (i-local)
        int c4 = (tid & 7) * 4;       // o-local
        float4 v = *reinterpret_cast<const float4*>(&g_SdT[(i0 + r) * NOUT + o0 + c4]);
        s_t[r][c4 + 0] = v.x; s_t[r][c4 + 1] = v.y;
        s_t[r][c4 + 2] = v.z; s_t[r][c4 + 3] = v.w;
    }
    __syncthreads();

    const float s = LR_LTP / (float)BATCH;
    const int ol = tid >> 3;          // o-local 0..31
    const int il = (tid & 7) * 4;     // i-local
    const int base = (o0 + ol) * NIN + i0 + il;
    float4 w = *reinterpret_cast<const float4*>(&weight[base]);
    float4 p = *reinterpret_cast<const float4*>(&g_Sp[base]);
    float4 r;
    r.x = s * ((1.f - w.x) * p.x - w.x * s_t[il + 0][ol]);
    r.y = s * ((1.f - w.y) * p.y - w.y * s_t[il + 1][ol]);
    r.z = s * ((1.f - w.z) * p.z - w.z * s_t[il + 2][ol]);
    r.w = s * ((1.f - w.w) * p.w - w.w * s_t[il + 3][ol]);
    *reinterpret_cast<float4*>(&delta_w[base]) = r;
}

// ---------------------------------------------------------------------------
extern "C" void kernel_launch(void* const* d_in, const int* in_sizes, int n_in,
                              void* d_out, int out_size)
{
    const float* weight      = (const float*)d_in[0];  // [NOUT, NIN]
    const float* pre_spikes  = (const float*)d_in[1];  // [T, B, NIN]
    const float* post_spikes = (const float*)d_in[2];  // [T, B, NOUT]
    const float* pre_trace0  = (const float*)d_in[3];  // [B, NIN]
    const float* post_trace0 = (const float*)d_in[4];  // [B, NOUT]

    float* out         = (float*)d_out;
    float* out_delta_w = out;                              // 512*1024
    float* out_pre_tr  = out + NOUT * NIN;                 // 32*1024
    float* out_post_tr = out + NOUT * NIN + BATCH * NIN;   // 32*512

    // 1) Fused trace recurrences + list builds (single pass, MLP=10)
    traces_fused_kernel<<<PRE_CTAS + POST_CTAS, 256>>>(
        pre_spikes, post_spikes, pre_trace0, post_trace0,
        out_pre_tr, out_post_tr);

    // 2) Both sparse gathers in one launch (coalesced stores both sides)
    gathers_fused_kernel<<<NIN + NOUT, 256>>>();

    // 3) Combine with tiled transpose of SdT
    dim3 cgrid(NIN / 32, NOUT / 32);
    combine_kernel<<<cgrid, 256>>>(weight, out_delta_w);
}